// round 15
// baseline (speedup 1.0000x reference)
#include <cuda_runtime.h>
#include <cuda_fp16.h>
#include <cstdint>
#include <math.h>

// ---------------------------------------------------------------------------
// Problem constants
// ---------------------------------------------------------------------------
#define S_LEN   2048
#define BATCH   4
#define DIM_    1024
#define D_INNER 2048
#define D_ST    16
#define M_ROWS  (BATCH * S_LEN)      // 8192
#define NCHUNK  16
#define LCHUNK  (S_LEN / NCHUNK)     // 128

// ---------------------------------------------------------------------------
// Scratch (static __device__ — no allocations allowed)
// Packed tile layouts (fp16, XOR-swizzled), 128-row tiles:
//   [tile][kt][r:128][seg p:8][8]   (p = s ^ (r&7))
// ---------------------------------------------------------------------------
__device__ float  g_xr [(size_t)M_ROWS * 4096];             // GEMM1 out: x_copy | res (fp32)
__device__ __half g_yh [(size_t)M_ROWS * D_INNER];          // packed scan output (GEMM2 A)
__device__ float  g_dA [M_ROWS * D_ST];
__device__ float  g_gs [M_ROWS];
__device__ float  g_Ap [BATCH * NCHUNK * D_ST];
__device__ float  g_hend[(size_t)BATCH * NCHUNK * D_INNER * D_ST];
__device__ float  g_hin [(size_t)BATCH * NCHUNK * D_INNER * D_ST];
__device__ __half g_xh [(size_t)M_ROWS * DIM_];             // packed x (GEMM1 A)
__device__ __half g_w1h[(size_t)4096 * DIM_];               // packed in_w
__device__ __half g_w2h[(size_t)DIM_ * D_INNER];            // packed out_w

// ---------------------------------------------------------------------------
// Helpers
// ---------------------------------------------------------------------------
__device__ __forceinline__ float sp_(float x) { return x > 20.f ? x : log1pf(expf(x)); }

__device__ __forceinline__ uint32_t s2u(const void* p) {
    uint32_t a;
    asm("{ .reg .u64 t; cvta.to.shared.u64 t, %1; cvt.u32.u64 %0, t; }" : "=r"(a) : "l"(p));
    return a;
}
__device__ __forceinline__ void mbar_init(uint32_t m, uint32_t cnt) {
    asm volatile("mbarrier.init.shared.b64 [%0], %1;" :: "r"(m), "r"(cnt) : "memory");
}
__device__ __forceinline__ void mbar_expect(uint32_t m, uint32_t bytes) {
    asm volatile("mbarrier.arrive.expect_tx.shared.b64 _, [%0], %1;" :: "r"(m), "r"(bytes) : "memory");
}
__device__ __forceinline__ void mbar_wait(uint32_t m, uint32_t parity) {
    asm volatile("{\n\t.reg .pred P;\n\tWL_%=:\n\t"
        "mbarrier.try_wait.parity.acquire.cta.shared::cta.b64 P, [%0], %1, 0x989680;\n\t"
        "@P bra.uni WD_%=;\n\tbra.uni WL_%=;\n\tWD_%=:\n\t}"
        :: "r"(m), "r"(parity) : "memory");
}
__device__ __forceinline__ void bulk_g2s(uint32_t dst, const void* src, uint32_t bytes, uint32_t mb) {
    asm volatile("cp.async.bulk.shared::cluster.global.mbarrier::complete_tx::bytes "
                 "[%0], [%1], %2, [%3];"
                 :: "r"(dst), "l"(src), "r"(bytes), "r"(mb) : "memory");
}
__device__ __forceinline__ void mma16(float* d, const uint32_t* a, const uint32_t* b) {
    asm volatile("mma.sync.aligned.m16n8k16.row.col.f32.f16.f16.f32 "
        "{%0,%1,%2,%3}, {%4,%5,%6,%7}, {%8,%9}, {%0,%1,%2,%3};"
        : "+f"(d[0]), "+f"(d[1]), "+f"(d[2]), "+f"(d[3])
        : "r"(a[0]), "r"(a[1]), "r"(a[2]), "r"(a[3]), "r"(b[0]), "r"(b[1]));
}
__device__ __forceinline__ void ldsm4(uint32_t& r0, uint32_t& r1, uint32_t& r2, uint32_t& r3,
                                      uint32_t addr) {
    asm volatile("ldmatrix.sync.aligned.m8n8.x4.shared.b16 {%0,%1,%2,%3}, [%4];"
        : "=r"(r0), "=r"(r1), "=r"(r2), "=r"(r3) : "r"(addr));
}

// ---------------------------------------------------------------------------
// fp32 -> packed fp16 (128-row tiles, XOR-swizzled), all three tensors in one
// launch. One 16B chunk per thread iteration.
// ---------------------------------------------------------------------------
__device__ __forceinline__ void pack_chunk(const float* __restrict__ in,
                                           __half* __restrict__ out,
                                           int K, int g)
{
    const int KC = K >> 3;
    const int KT = K >> 6;
    const int n = g / KC, ck = g - n * KC;
    const int kt = ck >> 3, sg = ck & 7;
    const int tile = n >> 7, r = n & 127;
    const int p = sg ^ (r & 7);
    const float4* s = (const float4*)(in + (size_t)n * K + ck * 8);
    float4 v0 = s[0], v1 = s[1];
    __half2 h0 = __floats2half2_rn(v0.x, v0.y);
    __half2 h1 = __floats2half2_rn(v0.z, v0.w);
    __half2 h2 = __floats2half2_rn(v1.x, v1.y);
    __half2 h3 = __floats2half2_rn(v1.z, v1.w);
    uint4 o;
    o.x = *(uint32_t*)&h0; o.y = *(uint32_t*)&h1;
    o.z = *(uint32_t*)&h2; o.w = *(uint32_t*)&h3;
    *(uint4*)(out + (((size_t)(tile * KT + kt) * 128 + r) << 6) + p * 8) = o;
}

#define NCH1 ((M_ROWS * DIM_) / 8)          // 1048576  (x,   K=1024)
#define NCH2 ((4096 * DIM_) / 8)            // 524288   (in_w, K=1024)
#define NCH3 ((DIM_ * D_INNER) / 8)         // 262144   (out_w, K=2048)

__global__ void k_pack3(const float* __restrict__ x, const float* __restrict__ w1,
                        const float* __restrict__ w2)
{
    __half* xh;  __half* w1h;  __half* w2h;
    xh  = g_xh;  w1h = g_w1h;  w2h = g_w2h;
    const int total = NCH1 + NCH2 + NCH3;
    for (int g = blockIdx.x * blockDim.x + threadIdx.x; g < total;
         g += gridDim.x * blockDim.x) {
        if (g < NCH1)              pack_chunk(x,  xh,  1024, g);
        else if (g < NCH1 + NCH2)  pack_chunk(w1, w1h, 1024, g - NCH1);
        else                       pack_chunk(w2, w2h, 2048, g - NCH1 - NCH2);
    }
}

// ---------------------------------------------------------------------------
// FP16 mma.sync GEMM fed by cp.async.bulk; 2 CTAs/SM for latency interleave
//  - 128x128 CTA tile, K-tile 64 halves, 3 stages, mbarrier completion
//  - 8 warps (2m x 4n), 64x32 warp tile (acc 64 regs -> fits 2 CTAs in RF)
//  - ldmatrix.x4 frag loads; swizzle baked into packed global layout
// ---------------------------------------------------------------------------
#define TILE_A_B 16384u
#define TILE_B_B 16384u
#define STG_B    32768u
#define NSTG     3
#define GSMEM_BYTES (NSTG * STG_B)            // 98304

template<int KT, int NN>
__global__ __launch_bounds__(256, 2)
void gemm_h(const __half* __restrict__ Ap, const __half* __restrict__ Wp,
            const float* __restrict__ bias, float* __restrict__ C)
{
    extern __shared__ __align__(128) __half smem_h[];
    __shared__ __align__(8) unsigned long long mbar[NSTG];
    const uint32_t sbu = s2u(smem_h);
    const uint32_t mbu = s2u(mbar);

    const int tid = threadIdx.x, lane = tid & 31, warp = tid >> 5;
    const int warpM = warp & 1, warpN = warp >> 1;      // 2m x 4n
    const int gID = lane >> 2, tig = lane & 3;
    const int mt = blockIdx.y, nt = blockIdx.x;

    if (tid == 0) {
        for (int s = 0; s < NSTG; s++) mbar_init(mbu + 8 * s, 1);
        asm volatile("fence.proxy.async.shared::cta;" ::: "memory");
    }
    __syncthreads();

    auto issue = [&](int t) {
        const int s = t % NSTG;
        const uint32_t mb = mbu + 8 * s;
        mbar_expect(mb, STG_B);
        bulk_g2s(sbu + s * STG_B,            Ap + ((size_t)(mt * KT + t) << 13), TILE_A_B, mb);
        bulk_g2s(sbu + s * STG_B + TILE_A_B, Wp + ((size_t)(nt * KT + t) << 13), TILE_B_B, mb);
    };
    if (tid == 0) { issue(0); issue(1); }

    const int rA  = warpM * 64 + (lane & 15);
    const int hiA = lane >> 4;
    const int swA = rA & 7;
    const int rB  = warpN * 32 + ((lane >> 4) & 1) * 8 + (lane & 7);
    const int hiB = (lane >> 3) & 1;
    const int swB = rB & 7;

    float acc[4][4][4];
#pragma unroll
    for (int i = 0; i < 4; i++)
#pragma unroll
        for (int j = 0; j < 4; j++)
#pragma unroll
            for (int q = 0; q < 4; q++) acc[i][j][q] = 0.f;

    for (int t = 0; t < KT; t++) {
        const int s = t % NSTG;
        mbar_wait(mbu + 8 * s, (t / NSTG) & 1);
        __syncthreads();
        if (tid == 0 && t + 2 < KT) issue(t + 2);

        const uint32_t sa = sbu + s * STG_B;
        const uint32_t sb = sa + TILE_A_B;
#pragma unroll
        for (int kk = 0; kk < 4; kk++) {
            uint32_t a[4][4], b[4][2];
            const uint32_t segA = (uint32_t)(((2 * kk + hiA) ^ swA) * 16);
            const uint32_t segB = (uint32_t)(((2 * kk + hiB) ^ swB) * 16);
#pragma unroll
            for (int mi = 0; mi < 4; mi++)
                ldsm4(a[mi][0], a[mi][1], a[mi][2], a[mi][3],
                      sa + (uint32_t)((rA + mi * 16) * 128) + segA);
#pragma unroll
            for (int jj = 0; jj < 2; jj++)
                ldsm4(b[2 * jj][0], b[2 * jj][1], b[2 * jj + 1][0], b[2 * jj + 1][1],
                      sb + (uint32_t)((rB + jj * 16) * 128) + segB);
#pragma unroll
            for (int mi = 0; mi < 4; mi++)
#pragma unroll
                for (int j = 0; j < 4; j++)
                    mma16(acc[mi][j], a[mi], b[j]);
        }
    }

    // ---- epilogue ----
#pragma unroll
    for (int mi = 0; mi < 4; mi++) {
        const int row0 = mt * 128 + warpM * 64 + mi * 16 + gID;
        const int col0 = nt * 128 + warpN * 32 + tig * 2;
#pragma unroll
        for (int j = 0; j < 4; j++) {
            const int cc = col0 + j * 8;
            const float b0 = __ldg(bias + cc), b1 = __ldg(bias + cc + 1);
            *(float2*)(C + (size_t)row0 * NN + cc) =
                make_float2(acc[mi][j][0] + b0, acc[mi][j][1] + b1);
            *(float2*)(C + (size_t)(row0 + 8) * NN + cc) =
                make_float2(acc[mi][j][2] + b0, acc[mi][j][3] + b1);
        }
    }
}

// ---------------------------------------------------------------------------
// Fused conv(depthwise,4) + gamma/delta projections -> dA, silu(gamma)
// 4 tokens per block.
// ---------------------------------------------------------------------------
__global__ __launch_bounds__(256)
void conv_proj(const float* __restrict__ conv_w, const float* __restrict__ conv_b,
               const float* __restrict__ xproj_w, const float* __restrict__ xproj_b,
               const float* __restrict__ dt_w, const float* __restrict__ dt_b,
               const float* __restrict__ Avec)
{
    const int m0 = blockIdx.x * 4;
    const int b = m0 >> 11, t0 = m0 & (S_LEN - 1);
    const int tid = threadIdx.x, lane = tid & 31, wid = tid >> 5;
    const float* xc = g_xr + (size_t)b * S_LEN * 4096;
    const float* w20 = xproj_w + 20 * D_INNER;

    float part[4][17];
#pragma unroll
    for (int tok = 0; tok < 4; tok++)
#pragma unroll
        for (int r = 0; r < 17; r++) part[tok][r] = 0.f;

#pragma unroll
    for (int g = 0; g < 2; g++) {
        const int d = (tid << 3) + (g << 2);
        float wmat[4][4];
#pragma unroll
        for (int q = 0; q < 4; q++) {
            float4 cwv = *(const float4*)(conv_w + (d + q) * 4);
            wmat[q][0] = cwv.x; wmat[q][1] = cwv.y; wmat[q][2] = cwv.z; wmat[q][3] = cwv.w;
        }
        float4 cbv = *(const float4*)(conv_b + d);
        float cs[4][4];
#pragma unroll
        for (int tok = 0; tok < 4; tok++) {
            cs[tok][0] = cbv.x; cs[tok][1] = cbv.y; cs[tok][2] = cbv.z; cs[tok][3] = cbv.w;
        }
#pragma unroll
        for (int rr = -1; rr <= 5; rr++) {
            const int tk = t0 + rr;
            if (tk >= 0 && tk < S_LEN) {
                float4 xv = *(const float4*)(xc + (size_t)tk * 4096 + d);
#pragma unroll
                for (int tok = 0; tok < 4; tok++) {
                    const int k = rr - tok + 1;
                    if (k >= 0 && k < 4) {
                        cs[tok][0] = fmaf(wmat[0][k], xv.x, cs[tok][0]);
                        cs[tok][1] = fmaf(wmat[1][k], xv.y, cs[tok][1]);
                        cs[tok][2] = fmaf(wmat[2][k], xv.z, cs[tok][2]);
                        cs[tok][3] = fmaf(wmat[3][k], xv.w, cs[tok][3]);
                    }
                }
            }
        }
        float4 wg = *(const float4*)(w20 + d);
#pragma unroll
        for (int tok = 0; tok < 4; tok++)
            part[tok][16] += cs[tok][0]*wg.x + cs[tok][1]*wg.y + cs[tok][2]*wg.z + cs[tok][3]*wg.w;
#pragma unroll
        for (int n = 0; n < 16; n++) {
            float4 wv = *(const float4*)(dt_w + n * D_INNER + d);
#pragma unroll
            for (int tok = 0; tok < 4; tok++)
                part[tok][n] = fmaf(cs[tok][0], wv.x, fmaf(cs[tok][1], wv.y,
                               fmaf(cs[tok][2], wv.z, fmaf(cs[tok][3], wv.w, part[tok][n]))));
        }
    }

    __shared__ float red[8][68];
#pragma unroll
    for (int tok = 0; tok < 4; tok++) {
#pragma unroll
        for (int r = 0; r < 17; r++) {
            float v = part[tok][r];
#pragma unroll
            for (int o = 16; o > 0; o >>= 1) v += __shfl_down_sync(0xffffffffu, v, o);
            if (lane == 0) red[wid][tok * 17 + r] = v;
        }
    }
    __syncthreads();
    if (tid < 68) {
        const int tok = tid / 17, r = tid - tok * 17;
        float s = 0.f;
#pragma unroll
        for (int w = 0; w < 8; w++) s += red[w][tid];
        if (r < 16) {
            const float delta = sp_(s + dt_b[r]);
            const float spA   = sp_(Avec[r]);
            g_dA[(m0 + tok) * D_ST + r] = expf(-delta * spA);
        } else {
            const float gamma = s + xproj_b[20];
            g_gs[m0 + tok] = gamma / (1.f + expf(-gamma));
        }
    }
}

// ---------------------------------------------------------------------------
// Scan pass 1 (local, zero-init) with smem-staged dA.
// Fused aprod: the (gid&7)==0 block of each (b,c) also writes g_Ap from s_a.
// ---------------------------------------------------------------------------
__global__ __launch_bounds__(256)
void scan_pass1(const float* __restrict__ Bm)
{
    __shared__ float s_a[LCHUNK * D_ST];    // 8 KB
    const int gid = blockIdx.x;
    const int d = ((gid & 7) << 8) + threadIdx.x;
    const int c = (gid >> 3) & (NCHUNK - 1);
    const int b = gid >> 7;
    const int m0 = b * S_LEN + c * LCHUNK;

    for (int i = threadIdx.x; i < LCHUNK * D_ST; i += 256) s_a[i] = g_dA[m0 * D_ST + i];
    __syncthreads();

    // fused per-chunk dA product (replaces aprod_kernel); threads 0..15 of the
    // first block for this (b,c) compute it while the rest run the scan below
    if ((gid & 7) == 0 && threadIdx.x < D_ST) {
        float p = 1.f;
        for (int i = 0; i < LCHUNK; i++) p *= s_a[i * D_ST + threadIdx.x];
        g_Ap[(b * NCHUNK + c) * D_ST + threadIdx.x] = p;
    }

    float dB[16];
#pragma unroll
    for (int q = 0; q < 4; q++) {
        float4 v = *(const float4*)(Bm + d * D_ST + 4 * q);
        dB[4*q+0] = sp_(v.x); dB[4*q+1] = sp_(v.y); dB[4*q+2] = sp_(v.z); dB[4*q+3] = sp_(v.w);
    }
    float h[16];
#pragma unroll
    for (int n = 0; n < 16; n++) h[n] = 0.f;

    const float* xp = g_xr + (size_t)m0 * 4096 + d;
    for (int i = 0; i < LCHUNK; i++) {
        const float u = __ldg(xp + (size_t)i * 4096);
#pragma unroll
        for (int q = 0; q < 4; q++) {
            float4 a4 = *(const float4*)(s_a + i * D_ST + 4 * q);
            h[4*q+0] = fmaf(h[4*q+0], a4.x, u * dB[4*q+0]);
            h[4*q+1] = fmaf(h[4*q+1], a4.y, u * dB[4*q+1]);
            h[4*q+2] = fmaf(h[4*q+2], a4.z, u * dB[4*q+2]);
            h[4*q+3] = fmaf(h[4*q+3], a4.w, u * dB[4*q+3]);
        }
    }
    const size_t o = ((size_t)(b * NCHUNK + c) * D_INNER + d) * D_ST;
#pragma unroll
    for (int q = 0; q < 4; q++)
        *(float4*)(g_hend + o + 4 * q) = make_float4(h[4*q], h[4*q+1], h[4*q+2], h[4*q+3]);
}

// ---------------------------------------------------------------------------
// Inter-chunk carry
// ---------------------------------------------------------------------------
__global__ void scan_carry()
{
    const int lin = blockIdx.x * 256 + threadIdx.x;
    const int n = lin & 15;
    const int d = (lin >> 4) & (D_INNER - 1);
    const int b = lin >> 15;
    float h = 0.f;
    for (int c = 0; c < NCHUNK; c++) {
        const size_t idx = ((size_t)(b * NCHUNK + c) * D_INNER + d) * D_ST + n;
        g_hin[idx] = h;
        h = h * g_Ap[(b * NCHUNK + c) * D_ST + n] + g_hend[idx];
    }
}

// ---------------------------------------------------------------------------
// Scan pass 2 -> packed fp16 y (GEMM2 A layout, 128-row tiles)
// ---------------------------------------------------------------------------
__global__ __launch_bounds__(256)
void scan_pass2(const float* __restrict__ Bm, const float* __restrict__ Cm)
{
    __shared__ float s_a[LCHUNK * D_ST];
    __shared__ float s_g[LCHUNK];
    const int gid = blockIdx.x;
    const int d = ((gid & 7) << 8) + threadIdx.x;
    const int c = (gid >> 3) & (NCHUNK - 1);
    const int b = gid >> 7;
    const int m0 = b * S_LEN + c * LCHUNK;

    for (int i = threadIdx.x; i < LCHUNK * D_ST; i += 256) s_a[i] = g_dA[m0 * D_ST + i];
    for (int i = threadIdx.x; i < LCHUNK; i += 256) s_g[i] = g_gs[m0 + i];
    __syncthreads();

    float dB[16], dC[16];
#pragma unroll
    for (int q = 0; q < 4; q++) {
        float4 v = *(const float4*)(Bm + d * D_ST + 4 * q);
        dB[4*q+0] = sp_(v.x); dB[4*q+1] = sp_(v.y); dB[4*q+2] = sp_(v.z); dB[4*q+3] = sp_(v.w);
        float4 w = *(const float4*)(Cm + d * D_ST + 4 * q);
        dC[4*q+0] = w.x; dC[4*q+1] = w.y; dC[4*q+2] = w.z; dC[4*q+3] = w.w;
    }
    const size_t o = ((size_t)(b * NCHUNK + c) * D_INNER + d) * D_ST;
    float h[16];
#pragma unroll
    for (int q = 0; q < 4; q++) {
        float4 v = *(const float4*)(g_hin + o + 4 * q);
        h[4*q+0] = v.x; h[4*q+1] = v.y; h[4*q+2] = v.z; h[4*q+3] = v.w;
    }

    const float* xp = g_xr + (size_t)m0 * 4096 + d;
    const float* rp = g_xr + (size_t)m0 * 4096 + D_INNER + d;

    // packed y indexing pieces (K=2048 -> 32 k-tiles; 128-row tiles)
    const int kt = d >> 6, sg = (d >> 3) & 7, e = d & 7;

    for (int i = 0; i < LCHUNK; i++) {
        const float u = __ldg(xp + (size_t)i * 4096);
        float y = 0.f;
#pragma unroll
        for (int q = 0; q < 4; q++) {
            float4 a4 = *(const float4*)(s_a + i * D_ST + 4 * q);
            h[4*q+0] = fmaf(h[4*q+0], a4.x, u * dB[4*q+0]);
            h[4*q+1] = fmaf(h[4*q+1], a4.y, u * dB[4*q+1]);
            h[4*q+2] = fmaf(h[4*q+2], a4.z, u * dB[4*q+2]);
            h[4*q+3] = fmaf(h[4*q+3], a4.w, u * dB[4*q+3]);
            y = fmaf(h[4*q+0], dC[4*q+0], y);
            y = fmaf(h[4*q+1], dC[4*q+1], y);
            y = fmaf(h[4*q+2], dC[4*q+2], y);
            y = fmaf(h[4*q+3], dC[4*q+3], y);
        }
        const int m = m0 + i;
        const int r = m & 127, mtile = m >> 7;
        const int p = sg ^ (r & 7);
        g_yh[(((size_t)(mtile * 32 + kt) * 128 + r) << 6) + p * 8 + e] =
            __float2half_rn(fmaf(y, s_g[i], __ldg(rp + (size_t)i * 4096)));
    }
}

// ---------------------------------------------------------------------------
// Launch
// ---------------------------------------------------------------------------
extern "C" void kernel_launch(void* const* d_in, const int* in_sizes, int n_in,
                              void* d_out, int out_size)
{
    const float* x       = (const float*)d_in[0];
    const float* in_w    = (const float*)d_in[1];
    const float* in_b    = (const float*)d_in[2];
    const float* conv_w  = (const float*)d_in[3];
    const float* conv_b  = (const float*)d_in[4];
    const float* xproj_w = (const float*)d_in[5];
    const float* xproj_b = (const float*)d_in[6];
    const float* dt_w    = (const float*)d_in[7];
    const float* dt_b    = (const float*)d_in[8];
    const float* A       = (const float*)d_in[9];
    const float* Bm      = (const float*)d_in[10];
    const float* Cm      = (const float*)d_in[11];
    const float* out_w   = (const float*)d_in[12];
    const float* out_b   = (const float*)d_in[13];
    float* out = (float*)d_out;

    float *xr;
    __half *xh, *w1h, *w2h, *yh;
    cudaGetSymbolAddress((void**)&xr,  g_xr);
    cudaGetSymbolAddress((void**)&xh,  g_xh);
    cudaGetSymbolAddress((void**)&w1h, g_w1h);
    cudaGetSymbolAddress((void**)&w2h, g_w2h);
    cudaGetSymbolAddress((void**)&yh,  g_yh);

    cudaFuncSetAttribute(gemm_h<16, 4096>, cudaFuncAttributeMaxDynamicSharedMemorySize, GSMEM_BYTES);
    cudaFuncSetAttribute(gemm_h<32, 1024>, cudaFuncAttributeMaxDynamicSharedMemorySize, GSMEM_BYTES);

    // fp32 -> packed/swizzled fp16 (all three tensors, one launch)
    k_pack3<<<1792, 256>>>(x, in_w, out_w);

    // GEMM1: g_xr = x @ in_w^T + in_b     [8192, 4096]
    gemm_h<16, 4096><<<dim3(4096 / 128, M_ROWS / 128), 256, GSMEM_BYTES>>>(xh, w1h, in_b, xr);

    // conv + projections -> dA, silu(gamma)   (4 tokens per block)
    conv_proj<<<M_ROWS / 4, 256>>>(conv_w, conv_b, xproj_w, xproj_b, dt_w, dt_b, A);

    // chunked scan (16 chunks of 128); aprod fused into pass1
    scan_pass1<<<BATCH * NCHUNK * (D_INNER / 256), 256>>>(Bm);
    scan_carry<<<(BATCH * D_INNER * D_ST) / 256, 256>>>();
    scan_pass2<<<BATCH * NCHUNK * (D_INNER / 256), 256>>>(Bm, Cm);

    // GEMM2: out = y @ out_w^T + out_b  [8192, 1024]
    gemm_h<32, 1024><<<dim3(1024 / 128, M_ROWS / 128), 256, GSMEM_BYTES>>>(yh, w2h, out_b, out);
}

// round 16
// speedup vs baseline: 1.0228x; 1.0228x over previous
#include <cuda_runtime.h>
#include <cuda_fp16.h>
#include <cstdint>
#include <math.h>

// ---------------------------------------------------------------------------
// Problem constants
// ---------------------------------------------------------------------------
#define S_LEN   2048
#define BATCH   4
#define DIM_    1024
#define D_INNER 2048
#define D_ST    16
#define M_ROWS  (BATCH * S_LEN)      // 8192
#define NCHUNK  16
#define LCHUNK  (S_LEN / NCHUNK)     // 128

// ---------------------------------------------------------------------------
// Scratch (static __device__ — no allocations allowed)
// Packed tile layouts (fp16, XOR-swizzled), 128-row tiles:
//   [tile][kt][r:128][seg p:8][8]   (p = s ^ (r&7))
// ---------------------------------------------------------------------------
__device__ float  g_xr [(size_t)M_ROWS * 4096];             // GEMM1 out: x_copy | res (fp32)
__device__ __half g_yh [(size_t)M_ROWS * D_INNER];          // packed scan output (GEMM2 A)
__device__ float  g_dA [M_ROWS * D_ST];
__device__ float  g_gs [M_ROWS];
__device__ float  g_Ap [BATCH * NCHUNK * D_ST];
__device__ float  g_hend[(size_t)BATCH * NCHUNK * D_INNER * D_ST];
__device__ float  g_hin [(size_t)BATCH * NCHUNK * D_INNER * D_ST];
__device__ __half g_xh [(size_t)M_ROWS * DIM_];             // packed x (GEMM1 A)
__device__ __half g_w1h[(size_t)4096 * DIM_];               // packed in_w
__device__ __half g_w2h[(size_t)DIM_ * D_INNER];            // packed out_w

// ---------------------------------------------------------------------------
// Helpers
// ---------------------------------------------------------------------------
__device__ __forceinline__ float sp_(float x) { return x > 20.f ? x : log1pf(expf(x)); }

__device__ __forceinline__ uint32_t s2u(const void* p) {
    uint32_t a;
    asm("{ .reg .u64 t; cvta.to.shared.u64 t, %1; cvt.u32.u64 %0, t; }" : "=r"(a) : "l"(p));
    return a;
}
__device__ __forceinline__ void mbar_init(uint32_t m, uint32_t cnt) {
    asm volatile("mbarrier.init.shared.b64 [%0], %1;" :: "r"(m), "r"(cnt) : "memory");
}
__device__ __forceinline__ void mbar_expect(uint32_t m, uint32_t bytes) {
    asm volatile("mbarrier.arrive.expect_tx.shared.b64 _, [%0], %1;" :: "r"(m), "r"(bytes) : "memory");
}
__device__ __forceinline__ void mbar_wait(uint32_t m, uint32_t parity) {
    asm volatile("{\n\t.reg .pred P;\n\tWL_%=:\n\t"
        "mbarrier.try_wait.parity.acquire.cta.shared::cta.b64 P, [%0], %1, 0x989680;\n\t"
        "@P bra.uni WD_%=;\n\tbra.uni WL_%=;\n\tWD_%=:\n\t}"
        :: "r"(m), "r"(parity) : "memory");
}
__device__ __forceinline__ void bulk_g2s(uint32_t dst, const void* src, uint32_t bytes, uint32_t mb) {
    asm volatile("cp.async.bulk.shared::cluster.global.mbarrier::complete_tx::bytes "
                 "[%0], [%1], %2, [%3];"
                 :: "r"(dst), "l"(src), "r"(bytes), "r"(mb) : "memory");
}
__device__ __forceinline__ void mma16(float* d, const uint32_t* a, const uint32_t* b) {
    asm volatile("mma.sync.aligned.m16n8k16.row.col.f32.f16.f16.f32 "
        "{%0,%1,%2,%3}, {%4,%5,%6,%7}, {%8,%9}, {%0,%1,%2,%3};"
        : "+f"(d[0]), "+f"(d[1]), "+f"(d[2]), "+f"(d[3])
        : "r"(a[0]), "r"(a[1]), "r"(a[2]), "r"(a[3]), "r"(b[0]), "r"(b[1]));
}
__device__ __forceinline__ void ldsm4(uint32_t& r0, uint32_t& r1, uint32_t& r2, uint32_t& r3,
                                      uint32_t addr) {
    asm volatile("ldmatrix.sync.aligned.m8n8.x4.shared.b16 {%0,%1,%2,%3}, [%4];"
        : "=r"(r0), "=r"(r1), "=r"(r2), "=r"(r3) : "r"(addr));
}

// ---------------------------------------------------------------------------
// fp32 -> packed fp16 (128-row tiles, XOR-swizzled), all three tensors in one
// launch. One 16B chunk per thread iteration.
// ---------------------------------------------------------------------------
__device__ __forceinline__ void pack_chunk(const float* __restrict__ in,
                                           __half* __restrict__ out,
                                           int K, int g)
{
    const int KC = K >> 3;
    const int KT = K >> 6;
    const int n = g / KC, ck = g - n * KC;
    const int kt = ck >> 3, sg = ck & 7;
    const int tile = n >> 7, r = n & 127;
    const int p = sg ^ (r & 7);
    const float4* s = (const float4*)(in + (size_t)n * K + ck * 8);
    float4 v0 = s[0], v1 = s[1];
    __half2 h0 = __floats2half2_rn(v0.x, v0.y);
    __half2 h1 = __floats2half2_rn(v0.z, v0.w);
    __half2 h2 = __floats2half2_rn(v1.x, v1.y);
    __half2 h3 = __floats2half2_rn(v1.z, v1.w);
    uint4 o;
    o.x = *(uint32_t*)&h0; o.y = *(uint32_t*)&h1;
    o.z = *(uint32_t*)&h2; o.w = *(uint32_t*)&h3;
    *(uint4*)(out + (((size_t)(tile * KT + kt) * 128 + r) << 6) + p * 8) = o;
}

#define NCH1 ((M_ROWS * DIM_) / 8)          // 1048576  (x,   K=1024)
#define NCH2 ((4096 * DIM_) / 8)            // 524288   (in_w, K=1024)
#define NCH3 ((DIM_ * D_INNER) / 8)         // 262144   (out_w, K=2048)

__global__ void k_pack3(const float* __restrict__ x, const float* __restrict__ w1,
                        const float* __restrict__ w2)
{
    __half* xh;  __half* w1h;  __half* w2h;
    xh  = g_xh;  w1h = g_w1h;  w2h = g_w2h;
    const int total = NCH1 + NCH2 + NCH3;
    for (int g = blockIdx.x * blockDim.x + threadIdx.x; g < total;
         g += gridDim.x * blockDim.x) {
        if (g < NCH1)              pack_chunk(x,  xh,  1024, g);
        else if (g < NCH1 + NCH2)  pack_chunk(w1, w1h, 1024, g - NCH1);
        else                       pack_chunk(w2, w2h, 2048, g - NCH1 - NCH2);
    }
}

// ---------------------------------------------------------------------------
// FP16 mma.sync GEMM fed by cp.async.bulk; 2 CTAs/SM for latency interleave
//  - 128x128 CTA tile, K-tile 64 halves, 3 stages, mbarrier completion
//  - 8 warps (2m x 4n), 64x32 warp tile (acc 64 regs -> fits 2 CTAs in RF)
//  - ldmatrix.x4 frag loads; swizzle baked into packed global layout
// ---------------------------------------------------------------------------
#define TILE_A_B 16384u
#define TILE_B_B 16384u
#define STG_B    32768u
#define NSTG     3
#define GSMEM_BYTES (NSTG * STG_B)            // 98304

template<int KT, int NN>
__global__ __launch_bounds__(256, 2)
void gemm_h(const __half* __restrict__ Ap, const __half* __restrict__ Wp,
            const float* __restrict__ bias, float* __restrict__ C)
{
    extern __shared__ __align__(128) __half smem_h[];
    __shared__ __align__(8) unsigned long long mbar[NSTG];
    const uint32_t sbu = s2u(smem_h);
    const uint32_t mbu = s2u(mbar);

    const int tid = threadIdx.x, lane = tid & 31, warp = tid >> 5;
    const int warpM = warp & 1, warpN = warp >> 1;      // 2m x 4n
    const int gID = lane >> 2, tig = lane & 3;
    const int mt = blockIdx.y, nt = blockIdx.x;

    if (tid == 0) {
        for (int s = 0; s < NSTG; s++) mbar_init(mbu + 8 * s, 1);
        asm volatile("fence.proxy.async.shared::cta;" ::: "memory");
    }
    __syncthreads();

    auto issue = [&](int t) {
        const int s = t % NSTG;
        const uint32_t mb = mbu + 8 * s;
        mbar_expect(mb, STG_B);
        bulk_g2s(sbu + s * STG_B,            Ap + ((size_t)(mt * KT + t) << 13), TILE_A_B, mb);
        bulk_g2s(sbu + s * STG_B + TILE_A_B, Wp + ((size_t)(nt * KT + t) << 13), TILE_B_B, mb);
    };
    if (tid == 0) { issue(0); issue(1); }

    const int rA  = warpM * 64 + (lane & 15);
    const int hiA = lane >> 4;
    const int swA = rA & 7;
    const int rB  = warpN * 32 + ((lane >> 4) & 1) * 8 + (lane & 7);
    const int hiB = (lane >> 3) & 1;
    const int swB = rB & 7;

    float acc[4][4][4];
#pragma unroll
    for (int i = 0; i < 4; i++)
#pragma unroll
        for (int j = 0; j < 4; j++)
#pragma unroll
            for (int q = 0; q < 4; q++) acc[i][j][q] = 0.f;

    for (int t = 0; t < KT; t++) {
        const int s = t % NSTG;
        mbar_wait(mbu + 8 * s, (t / NSTG) & 1);
        __syncthreads();
        if (tid == 0 && t + 2 < KT) issue(t + 2);

        const uint32_t sa = sbu + s * STG_B;
        const uint32_t sb = sa + TILE_A_B;
#pragma unroll
        for (int kk = 0; kk < 4; kk++) {
            uint32_t a[4][4], b[4][2];
            const uint32_t segA = (uint32_t)(((2 * kk + hiA) ^ swA) * 16);
            const uint32_t segB = (uint32_t)(((2 * kk + hiB) ^ swB) * 16);
#pragma unroll
            for (int mi = 0; mi < 4; mi++)
                ldsm4(a[mi][0], a[mi][1], a[mi][2], a[mi][3],
                      sa + (uint32_t)((rA + mi * 16) * 128) + segA);
#pragma unroll
            for (int jj = 0; jj < 2; jj++)
                ldsm4(b[2 * jj][0], b[2 * jj][1], b[2 * jj + 1][0], b[2 * jj + 1][1],
                      sb + (uint32_t)((rB + jj * 16) * 128) + segB);
#pragma unroll
            for (int mi = 0; mi < 4; mi++)
#pragma unroll
                for (int j = 0; j < 4; j++)
                    mma16(acc[mi][j], a[mi], b[j]);
        }
    }

    // ---- epilogue ----
#pragma unroll
    for (int mi = 0; mi < 4; mi++) {
        const int row0 = mt * 128 + warpM * 64 + mi * 16 + gID;
        const int col0 = nt * 128 + warpN * 32 + tig * 2;
#pragma unroll
        for (int j = 0; j < 4; j++) {
            const int cc = col0 + j * 8;
            const float b0 = __ldg(bias + cc), b1 = __ldg(bias + cc + 1);
            *(float2*)(C + (size_t)row0 * NN + cc) =
                make_float2(acc[mi][j][0] + b0, acc[mi][j][1] + b1);
            *(float2*)(C + (size_t)(row0 + 8) * NN + cc) =
                make_float2(acc[mi][j][2] + b0, acc[mi][j][3] + b1);
        }
    }
}

// ---------------------------------------------------------------------------
// Fused conv(depthwise,4) + gamma/delta projections -> dA, silu(gamma)
// 4 tokens per block.
// ---------------------------------------------------------------------------
__global__ __launch_bounds__(256)
void conv_proj(const float* __restrict__ conv_w, const float* __restrict__ conv_b,
               const float* __restrict__ xproj_w, const float* __restrict__ xproj_b,
               const float* __restrict__ dt_w, const float* __restrict__ dt_b,
               const float* __restrict__ Avec)
{
    const int m0 = blockIdx.x * 4;
    const int b = m0 >> 11, t0 = m0 & (S_LEN - 1);
    const int tid = threadIdx.x, lane = tid & 31, wid = tid >> 5;
    const float* xc = g_xr + (size_t)b * S_LEN * 4096;
    const float* w20 = xproj_w + 20 * D_INNER;

    float part[4][17];
#pragma unroll
    for (int tok = 0; tok < 4; tok++)
#pragma unroll
        for (int r = 0; r < 17; r++) part[tok][r] = 0.f;

#pragma unroll
    for (int g = 0; g < 2; g++) {
        const int d = (tid << 3) + (g << 2);
        float wmat[4][4];
#pragma unroll
        for (int q = 0; q < 4; q++) {
            float4 cwv = *(const float4*)(conv_w + (d + q) * 4);
            wmat[q][0] = cwv.x; wmat[q][1] = cwv.y; wmat[q][2] = cwv.z; wmat[q][3] = cwv.w;
        }
        float4 cbv = *(const float4*)(conv_b + d);
        float cs[4][4];
#pragma unroll
        for (int tok = 0; tok < 4; tok++) {
            cs[tok][0] = cbv.x; cs[tok][1] = cbv.y; cs[tok][2] = cbv.z; cs[tok][3] = cbv.w;
        }
#pragma unroll
        for (int rr = -1; rr <= 5; rr++) {
            const int tk = t0 + rr;
            if (tk >= 0 && tk < S_LEN) {
                float4 xv = *(const float4*)(xc + (size_t)tk * 4096 + d);
#pragma unroll
                for (int tok = 0; tok < 4; tok++) {
                    const int k = rr - tok + 1;
                    if (k >= 0 && k < 4) {
                        cs[tok][0] = fmaf(wmat[0][k], xv.x, cs[tok][0]);
                        cs[tok][1] = fmaf(wmat[1][k], xv.y, cs[tok][1]);
                        cs[tok][2] = fmaf(wmat[2][k], xv.z, cs[tok][2]);
                        cs[tok][3] = fmaf(wmat[3][k], xv.w, cs[tok][3]);
                    }
                }
            }
        }
        float4 wg = *(const float4*)(w20 + d);
#pragma unroll
        for (int tok = 0; tok < 4; tok++)
            part[tok][16] += cs[tok][0]*wg.x + cs[tok][1]*wg.y + cs[tok][2]*wg.z + cs[tok][3]*wg.w;
#pragma unroll
        for (int n = 0; n < 16; n++) {
            float4 wv = *(const float4*)(dt_w + n * D_INNER + d);
#pragma unroll
            for (int tok = 0; tok < 4; tok++)
                part[tok][n] = fmaf(cs[tok][0], wv.x, fmaf(cs[tok][1], wv.y,
                               fmaf(cs[tok][2], wv.z, fmaf(cs[tok][3], wv.w, part[tok][n]))));
        }
    }

    __shared__ float red[8][68];
#pragma unroll
    for (int tok = 0; tok < 4; tok++) {
#pragma unroll
        for (int r = 0; r < 17; r++) {
            float v = part[tok][r];
#pragma unroll
            for (int o = 16; o > 0; o >>= 1) v += __shfl_down_sync(0xffffffffu, v, o);
            if (lane == 0) red[wid][tok * 17 + r] = v;
        }
    }
    __syncthreads();
    if (tid < 68) {
        const int tok = tid / 17, r = tid - tok * 17;
        float s = 0.f;
#pragma unroll
        for (int w = 0; w < 8; w++) s += red[w][tid];
        if (r < 16) {
            const float delta = sp_(s + dt_b[r]);
            const float spA   = sp_(Avec[r]);
            g_dA[(m0 + tok) * D_ST + r] = expf(-delta * spA);
        } else {
            const float gamma = s + xproj_b[20];
            g_gs[m0 + tok] = gamma / (1.f + expf(-gamma));
        }
    }
}

// ---------------------------------------------------------------------------
// Per-chunk products of dA — parallel version.
// Block = (b,c): 256 threads = 16 token-groups x 16 n. Each thread multiplies
// 8 tokens, then a smem tree combines the 16 group partials.
// ---------------------------------------------------------------------------
__global__ __launch_bounds__(256)
void aprod_kernel()
{
    __shared__ float sp[16][16];          // [group][n]
    const int bc = blockIdx.x;
    const int n = threadIdx.x & 15;
    const int grp = threadIdx.x >> 4;     // 0..15, 8 tokens each
    const int b = bc / NCHUNK, c = bc % NCHUNK;
    const int base = (b * S_LEN + c * LCHUNK + grp * 8) * D_ST + n;
    float p = 1.f;
#pragma unroll
    for (int i = 0; i < 8; i++) p *= g_dA[base + i * D_ST];
    sp[grp][n] = p;
    __syncthreads();
    if (threadIdx.x < 16) {               // n = threadIdx.x
        float q = 1.f;
#pragma unroll
        for (int g = 0; g < 16; g++) q *= sp[g][threadIdx.x];
        g_Ap[bc * D_ST + threadIdx.x] = q;
    }
}

// ---------------------------------------------------------------------------
// Scan pass 1 (local, zero-init) with smem-staged dA
// ---------------------------------------------------------------------------
__global__ __launch_bounds__(256)
void scan_pass1(const float* __restrict__ Bm)
{
    __shared__ float s_a[LCHUNK * D_ST];    // 8 KB
    const int gid = blockIdx.x;
    const int d = ((gid & 7) << 8) + threadIdx.x;
    const int c = (gid >> 3) & (NCHUNK - 1);
    const int b = gid >> 7;
    const int m0 = b * S_LEN + c * LCHUNK;

    for (int i = threadIdx.x; i < LCHUNK * D_ST; i += 256) s_a[i] = g_dA[m0 * D_ST + i];
    __syncthreads();

    float dB[16];
#pragma unroll
    for (int q = 0; q < 4; q++) {
        float4 v = *(const float4*)(Bm + d * D_ST + 4 * q);
        dB[4*q+0] = sp_(v.x); dB[4*q+1] = sp_(v.y); dB[4*q+2] = sp_(v.z); dB[4*q+3] = sp_(v.w);
    }
    float h[16];
#pragma unroll
    for (int n = 0; n < 16; n++) h[n] = 0.f;

    const float* xp = g_xr + (size_t)m0 * 4096 + d;
    for (int i = 0; i < LCHUNK; i++) {
        const float u = __ldg(xp + (size_t)i * 4096);
#pragma unroll
        for (int q = 0; q < 4; q++) {
            float4 a4 = *(const float4*)(s_a + i * D_ST + 4 * q);
            h[4*q+0] = fmaf(h[4*q+0], a4.x, u * dB[4*q+0]);
            h[4*q+1] = fmaf(h[4*q+1], a4.y, u * dB[4*q+1]);
            h[4*q+2] = fmaf(h[4*q+2], a4.z, u * dB[4*q+2]);
            h[4*q+3] = fmaf(h[4*q+3], a4.w, u * dB[4*q+3]);
        }
    }
    const size_t o = ((size_t)(b * NCHUNK + c) * D_INNER + d) * D_ST;
#pragma unroll
    for (int q = 0; q < 4; q++)
        *(float4*)(g_hend + o + 4 * q) = make_float4(h[4*q], h[4*q+1], h[4*q+2], h[4*q+3]);
}

// ---------------------------------------------------------------------------
// Inter-chunk carry
// ---------------------------------------------------------------------------
__global__ void scan_carry()
{
    const int lin = blockIdx.x * 256 + threadIdx.x;
    const int n = lin & 15;
    const int d = (lin >> 4) & (D_INNER - 1);
    const int b = lin >> 15;
    float h = 0.f;
    for (int c = 0; c < NCHUNK; c++) {
        const size_t idx = ((size_t)(b * NCHUNK + c) * D_INNER + d) * D_ST + n;
        g_hin[idx] = h;
        h = h * g_Ap[(b * NCHUNK + c) * D_ST + n] + g_hend[idx];
    }
}

// ---------------------------------------------------------------------------
// Scan pass 2 -> packed fp16 y (GEMM2 A layout, 128-row tiles)
// ---------------------------------------------------------------------------
__global__ __launch_bounds__(256)
void scan_pass2(const float* __restrict__ Bm, const float* __restrict__ Cm)
{
    __shared__ float s_a[LCHUNK * D_ST];
    __shared__ float s_g[LCHUNK];
    const int gid = blockIdx.x;
    const int d = ((gid & 7) << 8) + threadIdx.x;
    const int c = (gid >> 3) & (NCHUNK - 1);
    const int b = gid >> 7;
    const int m0 = b * S_LEN + c * LCHUNK;

    for (int i = threadIdx.x; i < LCHUNK * D_ST; i += 256) s_a[i] = g_dA[m0 * D_ST + i];
    for (int i = threadIdx.x; i < LCHUNK; i += 256) s_g[i] = g_gs[m0 + i];
    __syncthreads();

    float dB[16], dC[16];
#pragma unroll
    for (int q = 0; q < 4; q++) {
        float4 v = *(const float4*)(Bm + d * D_ST + 4 * q);
        dB[4*q+0] = sp_(v.x); dB[4*q+1] = sp_(v.y); dB[4*q+2] = sp_(v.z); dB[4*q+3] = sp_(v.w);
        float4 w = *(const float4*)(Cm + d * D_ST + 4 * q);
        dC[4*q+0] = w.x; dC[4*q+1] = w.y; dC[4*q+2] = w.z; dC[4*q+3] = w.w;
    }
    const size_t o = ((size_t)(b * NCHUNK + c) * D_INNER + d) * D_ST;
    float h[16];
#pragma unroll
    for (int q = 0; q < 4; q++) {
        float4 v = *(const float4*)(g_hin + o + 4 * q);
        h[4*q+0] = v.x; h[4*q+1] = v.y; h[4*q+2] = v.z; h[4*q+3] = v.w;
    }

    const float* xp = g_xr + (size_t)m0 * 4096 + d;
    const float* rp = g_xr + (size_t)m0 * 4096 + D_INNER + d;

    // packed y indexing pieces (K=2048 -> 32 k-tiles; 128-row tiles)
    const int kt = d >> 6, sg = (d >> 3) & 7, e = d & 7;

    for (int i = 0; i < LCHUNK; i++) {
        const float u = __ldg(xp + (size_t)i * 4096);
        float y = 0.f;
#pragma unroll
        for (int q = 0; q < 4; q++) {
            float4 a4 = *(const float4*)(s_a + i * D_ST + 4 * q);
            h[4*q+0] = fmaf(h[4*q+0], a4.x, u * dB[4*q+0]);
            h[4*q+1] = fmaf(h[4*q+1], a4.y, u * dB[4*q+1]);
            h[4*q+2] = fmaf(h[4*q+2], a4.z, u * dB[4*q+2]);
            h[4*q+3] = fmaf(h[4*q+3], a4.w, u * dB[4*q+3]);
            y = fmaf(h[4*q+0], dC[4*q+0], y);
            y = fmaf(h[4*q+1], dC[4*q+1], y);
            y = fmaf(h[4*q+2], dC[4*q+2], y);
            y = fmaf(h[4*q+3], dC[4*q+3], y);
        }
        const int m = m0 + i;
        const int r = m & 127, mtile = m >> 7;
        const int p = sg ^ (r & 7);
        g_yh[(((size_t)(mtile * 32 + kt) * 128 + r) << 6) + p * 8 + e] =
            __float2half_rn(fmaf(y, s_g[i], __ldg(rp + (size_t)i * 4096)));
    }
}

// ---------------------------------------------------------------------------
// Launch
// ---------------------------------------------------------------------------
extern "C" void kernel_launch(void* const* d_in, const int* in_sizes, int n_in,
                              void* d_out, int out_size)
{
    const float* x       = (const float*)d_in[0];
    const float* in_w    = (const float*)d_in[1];
    const float* in_b    = (const float*)d_in[2];
    const float* conv_w  = (const float*)d_in[3];
    const float* conv_b  = (const float*)d_in[4];
    const float* xproj_w = (const float*)d_in[5];
    const float* xproj_b = (const float*)d_in[6];
    const float* dt_w    = (const float*)d_in[7];
    const float* dt_b    = (const float*)d_in[8];
    const float* A       = (const float*)d_in[9];
    const float* Bm      = (const float*)d_in[10];
    const float* Cm      = (const float*)d_in[11];
    const float* out_w   = (const float*)d_in[12];
    const float* out_b   = (const float*)d_in[13];
    float* out = (float*)d_out;

    float *xr;
    __half *xh, *w1h, *w2h, *yh;
    cudaGetSymbolAddress((void**)&xr,  g_xr);
    cudaGetSymbolAddress((void**)&xh,  g_xh);
    cudaGetSymbolAddress((void**)&w1h, g_w1h);
    cudaGetSymbolAddress((void**)&w2h, g_w2h);
    cudaGetSymbolAddress((void**)&yh,  g_yh);

    cudaFuncSetAttribute(gemm_h<16, 4096>, cudaFuncAttributeMaxDynamicSharedMemorySize, GSMEM_BYTES);
    cudaFuncSetAttribute(gemm_h<32, 1024>, cudaFuncAttributeMaxDynamicSharedMemorySize, GSMEM_BYTES);

    // fp32 -> packed/swizzled fp16 (all three tensors, one launch)
    k_pack3<<<1792, 256>>>(x, in_w, out_w);

    // GEMM1: g_xr = x @ in_w^T + in_b     [8192, 4096]
    gemm_h<16, 4096><<<dim3(4096 / 128, M_ROWS / 128), 256, GSMEM_BYTES>>>(xh, w1h, in_b, xr);

    // conv + projections -> dA, silu(gamma)   (4 tokens per block)
    conv_proj<<<M_ROWS / 4, 256>>>(conv_w, conv_b, xproj_w, xproj_b, dt_w, dt_b, A);

    // chunked scan (16 chunks of 128)
    aprod_kernel<<<BATCH * NCHUNK, 256>>>();
    scan_pass1<<<BATCH * NCHUNK * (D_INNER / 256), 256>>>(Bm);
    scan_carry<<<(BATCH * D_INNER * D_ST) / 256, 256>>>();
    scan_pass2<<<BATCH * NCHUNK * (D_INNER / 256), 256>>>(Bm, Cm);

    // GEMM2: out = y @ out_w^T + out_b  [8192, 1024]
    gemm_h<32, 1024><<<dim3(1024 / 128, M_ROWS / 128), 256, GSMEM_BYTES>>>(yh, w2h, out_b, out);
}